// round 4
// baseline (speedup 1.0000x reference)
#include <cuda_runtime.h>
#include <cuda_bf16.h>
#include <math.h>

#define BATCH    32
#define SRC_LEN  2048
#define DIM      1024
#define SBLK     32                     // s-rows per block
#define BPB      (SRC_LEN / SBLK)       // 64 blocks per batch row
#define GRID     (BATCH * BPB)          // 2048
#define THREADS  256
#define NWARP    (THREADS / 32)         // 8
#define RPW      (SBLK / NWARP)         // 4 rows per warp (sequential)

// Per-batch retirement counters. atomicInc wraps at BPB-1 -> returns to 0
// after every complete run, so graph replays start from a clean state.
__device__ unsigned int g_cnt[BATCH];

__global__ void __launch_bounds__(THREADS)
fused_attn_kernel(const float* __restrict__ dec_hidden,
                  const float* __restrict__ enc,
                  const float* __restrict__ W,
                  const float* __restrict__ bias,
                  float* __restrict__ out)
{
    __shared__ float4 s_wenc[DIM / 4];          // 4 KB
    __shared__ float  red[NWARP];
    __shared__ float  s_scalar;                 // e_dec, then row sum
    __shared__ int    s_last;

    const int b    = blockIdx.x & 31;           // batch
    const int j    = blockIdx.x >> 5;           // s-chunk within batch
    const int tid  = threadIdx.x;
    const int lane = tid & 31;
    const int warp = tid >> 5;

    // ---- stage w_enc (W[0,1024:2048]) in shared ----
    const float4* we_g = reinterpret_cast<const float4*>(W + DIM);
    for (int i = tid; i < DIM / 4; i += THREADS)
        s_wenc[i] = we_g[i];

    // ---- e_dec[b] = dec_hidden[b,:] . W[0,0:1024]  (256 thr x float4) ----
    {
        const float4* dh = reinterpret_cast<const float4*>(dec_hidden + (size_t)b * DIM);
        const float4* wd = reinterpret_cast<const float4*>(W);
        float4 a = dh[tid];
        float4 w = wd[tid];
        float ed = a.x * w.x + a.y * w.y + a.z * w.z + a.w * w.w;
#pragma unroll
        for (int o = 16; o > 0; o >>= 1)
            ed += __shfl_xor_sync(0xFFFFFFFFu, ed, o);
        if (lane == 0) red[warp] = ed;
    }
    __syncthreads();
    if (tid == 0) {
        float t = 0.f;
#pragma unroll
        for (int i = 0; i < NWARP; ++i) t += red[i];
        s_scalar = t + bias[0];
    }
    __syncthreads();
    const float edec = s_scalar;

    // ---- score phase: 1 row per warp per iteration (R1-style) ----
    const int s_base = j * SBLK + warp * RPW;
    for (int r = 0; r < RPW; ++r) {
        const int s = s_base + r;
        const float4* row = reinterpret_cast<const float4*>(
            enc + ((size_t)s * BATCH + b) * DIM);

        float acc = 0.f;
#pragma unroll
        for (int i = 0; i < 8; ++i) {           // 8 independent float4 streams
            float4 v = __ldcs(&row[lane + i * 32]);
            float4 w = s_wenc[lane + i * 32];
            acc += v.x * w.x + v.y * w.y + v.z * w.z + v.w * w.w;
        }
#pragma unroll
        for (int o = 16; o > 0; o >>= 1)
            acc += __shfl_xor_sync(0xFFFFFFFFu, acc, o);

        if (lane == 0)  // tanh in [-1,1] => exp safe without max subtraction
            out[(size_t)b * SRC_LEN + s] = __expf(tanhf(acc + edec));
    }

    // ---- retire; last block of batch b normalizes the row ----
    __threadfence();             // make this block's exp stores device-visible
    __syncthreads();
    if (tid == 0) {
        unsigned v = atomicInc(&g_cnt[b], BPB - 1);   // wraps to 0 each run
        s_last = (v == BPB - 1);
    }
    __syncthreads();
    if (!s_last) return;

    // normalize out[b, :] (8 KB, hot in L2)
    float* rowp = out + (size_t)b * SRC_LEN;
    float v[SRC_LEN / THREADS];                 // 8 values per thread
    float sum = 0.f;
#pragma unroll
    for (int i = 0; i < SRC_LEN / THREADS; ++i) {
        v[i] = __ldcg(&rowp[tid + i * THREADS]);   // bypass (possibly stale) L1
        sum += v[i];
    }
#pragma unroll
    for (int o = 16; o > 0; o >>= 1)
        sum += __shfl_xor_sync(0xFFFFFFFFu, sum, o);
    if (lane == 0) red[warp] = sum;
    __syncthreads();
    if (tid == 0) {
        float t = 0.f;
#pragma unroll
        for (int i = 0; i < NWARP; ++i) t += red[i];
        s_scalar = t;
    }
    __syncthreads();
    const float inv = 1.0f / s_scalar;

#pragma unroll
    for (int i = 0; i < SRC_LEN / THREADS; ++i)
        rowp[tid + i * THREADS] = v[i] * inv;
}

// ---------------------------------------------------------------------------
extern "C" void kernel_launch(void* const* d_in, const int* in_sizes, int n_in,
                              void* d_out, int out_size)
{
    const float* dec_hidden  = (const float*)d_in[0];   // (32, 1024)
    const float* enc_outputs = (const float*)d_in[1];   // (2048, 32, 1024)
    const float* W           = (const float*)d_in[2];   // (1, 2048)
    const float* bias        = (const float*)d_in[3];   // (1,)
    float* out = (float*)d_out;                          // (32, 2048)

    fused_attn_kernel<<<GRID, THREADS>>>(dec_hidden, enc_outputs, W, bias, out);
}